// round 10
// baseline (speedup 1.0000x reference)
#include <cuda_runtime.h>
#include <cuda_fp16.h>
#include <math.h>
#include <stdint.h>

#define B_ 4
#define S_ 2048
#define D_ 1024
#define H_ 2048
#define E_ 8
#define NTOK (B_*S_)            /* 8192  */
#define NPAD_MAX 17408          /* 16384 + 8*128 */
#define MTILES (NPAD_MAX/128)   /* 136 */
#define MU_F 0.7f
#define GAMMA_F 1.0f
#define LN_EPS_F 1e-5f

// ------------------------------------------------------------------
// scratch (static __device__; referenced ONLY from device code)
// ------------------------------------------------------------------
__device__ __align__(256) __half g_a1 [(size_t)NPAD_MAX * D_];
__device__ __align__(256) __half g_a2 [(size_t)NPAD_MAX * H_];
__device__ __align__(256) __half g_w1t[(size_t)E_ * H_ * D_];   // [e][h][d]
__device__ __align__(256) __half g_w2t[(size_t)E_ * D_ * H_];   // [e][d][h]
__device__ __align__(256) float  g_eo [(size_t)NPAD_MAX * D_];
__device__ int   g_assign_tok[NPAD_MAX];
__device__ int   g_slot [NTOK * 2];
__device__ float g_wk   [NTOK * 2];
__device__ int   g_eidx [NTOK * 2];
__device__ int   g_counts [E_];
__device__ int   g_offsets_pad[E_];
__device__ int   g_cursor [E_];

// ------------------------------------------------------------------
// PTX helpers
// ------------------------------------------------------------------
__device__ __forceinline__ uint32_t smem_u32(const void* p) {
    uint32_t a;
    asm("{ .reg .u64 t; cvta.to.shared.u64 t, %1; cvt.u32.u64 %0, t; }" : "=r"(a) : "l"(p));
    return a;
}
#define CP_ASYNC16(dst, src) \
    asm volatile("cp.async.cg.shared.global [%0], [%1], 16;" :: "r"(dst), "l"(src) : "memory")
#define CP_COMMIT() asm volatile("cp.async.commit_group;" ::: "memory")
#define CP_WAIT2()  asm volatile("cp.async.wait_group 2;"  ::: "memory")
#define CP_WAIT0()  asm volatile("cp.async.wait_group 0;"  ::: "memory")

#define LDSM4(r0, r1, r2, r3, addr) \
    asm volatile("ldmatrix.sync.aligned.m8n8.x4.shared.b16 {%0,%1,%2,%3}, [%4];" \
                 : "=r"(r0), "=r"(r1), "=r"(r2), "=r"(r3) : "r"(addr))

__device__ __forceinline__ void mma_f16(float& c0, float& c1, float& c2, float& c3,
                                        uint32_t a0, uint32_t a1, uint32_t a2, uint32_t a3,
                                        uint32_t b0, uint32_t b1) {
    asm volatile("mma.sync.aligned.m16n8k16.row.col.f32.f16.f16.f32 "
                 "{%0,%1,%2,%3}, {%4,%5,%6,%7}, {%8,%9}, {%0,%1,%2,%3};"
                 : "+f"(c0), "+f"(c1), "+f"(c2), "+f"(c3)
                 : "r"(a0), "r"(a1), "r"(a2), "r"(a3), "r"(b0), "r"(b1));
}

// ------------------------------------------------------------------
// routing kernels
// ------------------------------------------------------------------
__global__ void init_kernel() {
    int i = blockIdx.x * blockDim.x + threadIdx.x;
    if (i < E_) g_counts[i] = 0;
    if (i < NPAD_MAX) g_assign_tok[i] = -1;
}

__global__ void router_kernel(const float* __restrict__ x,
                              const float* __restrict__ Wg,
                              const float* __restrict__ bg) {
    int gwarp = (blockIdx.x * blockDim.x + threadIdx.x) >> 5;
    int lane  = threadIdx.x & 31;
    if (gwarp >= NTOK) return;
    const float* xr = x + (size_t)gwarp * D_;
    float acc[E_];
#pragma unroll
    for (int e = 0; e < E_; e++) acc[e] = 0.f;
    for (int d = lane; d < D_; d += 32) {
        float xv = xr[d];
        const float4* wr = reinterpret_cast<const float4*>(Wg + (size_t)d * E_);
        float4 w0 = wr[0], w1 = wr[1];
        acc[0] += xv * w0.x; acc[1] += xv * w0.y; acc[2] += xv * w0.z; acc[3] += xv * w0.w;
        acc[4] += xv * w1.x; acc[5] += xv * w1.y; acc[6] += xv * w1.z; acc[7] += xv * w1.w;
    }
#pragma unroll
    for (int e = 0; e < E_; e++)
#pragma unroll
        for (int o = 16; o > 0; o >>= 1)
            acc[e] += __shfl_xor_sync(0xffffffffu, acc[e], o);
    if (lane == 0) {
        float lg[E_];
#pragma unroll
        for (int e = 0; e < E_; e++) lg[e] = acc[e] + bg[e];
        int i0 = 0;
#pragma unroll
        for (int e = 1; e < E_; e++) if (lg[e] > lg[i0]) i0 = e;
        int i1 = -1;
#pragma unroll
        for (int e = 0; e < E_; e++) {
            if (e == i0) continue;
            if (i1 < 0 || lg[e] > lg[i1]) i1 = e;
        }
        float e1 = __expf(lg[i1] - lg[i0]);
        float inv = 1.f / (1.f + e1);
        g_eidx[gwarp*2]   = i0;  g_eidx[gwarp*2+1] = i1;
        g_wk  [gwarp*2]   = inv; g_wk  [gwarp*2+1] = e1 * inv;
        atomicAdd(&g_counts[i0], 1);
        atomicAdd(&g_counts[i1], 1);
    }
}

__global__ void offsets_kernel() {
    if (threadIdx.x == 0) {
        int acc = 0;
        for (int e = 0; e < E_; e++) {
            g_offsets_pad[e] = acc;
            g_cursor[e]      = acc;
            acc += (g_counts[e] + 127) & ~127;
        }
    }
}

__global__ void scatter_kernel() {
    int t = blockIdx.x * blockDim.x + threadIdx.x;
    if (t >= NTOK) return;
#pragma unroll
    for (int k = 0; k < 2; k++) {
        int e = g_eidx[t*2 + k];
        int pos = atomicAdd(&g_cursor[e], 1);
        g_assign_tok[pos] = t;
        g_slot[t*2 + k] = pos;
    }
}

// gather x rows into padded fp16 A1 (zeros for pad rows)
__global__ void gather_half_kernel(const float* __restrict__ x) {
    int slot = blockIdx.x;
    int t = g_assign_tok[slot];
    int d4 = threadIdx.x;                // 256 threads x 4 elems = 1024
    uint2 pk = make_uint2(0u, 0u);
    if (t >= 0) {
        float4 v = reinterpret_cast<const float4*>(x + (size_t)t * D_)[d4];
        __half2 p0 = __floats2half2_rn(v.x, v.y);
        __half2 p1 = __floats2half2_rn(v.z, v.w);
        pk.x = *reinterpret_cast<uint32_t*>(&p0);
        pk.y = *reinterpret_cast<uint32_t*>(&p1);
    }
    reinterpret_cast<uint2*>(g_a1 + (size_t)slot * D_)[d4] = pk;
}

// transpose + fp16 weights: in [e][RIN][CIN] -> out [e][CIN][RIN]
template<int RIN, int CIN, bool W1SEL>
__global__ void wtrans_half_kernel(const float* __restrict__ W) {
    __shared__ float tile[32][33];
    int e = blockIdx.z;
    int x0 = blockIdx.x * 32, y0 = blockIdx.y * 32;
    int tx = threadIdx.x, ty = threadIdx.y;  // 32 x 8
    const float* in = W + (size_t)e * RIN * CIN;
#pragma unroll
    for (int i = 0; i < 4; i++)
        tile[ty + i*8][tx] = in[(size_t)(y0 + ty + i*8) * CIN + x0 + tx];
    __syncthreads();
    __half* ot = W1SEL ? g_w1t : g_w2t;
    size_t ob = (size_t)e * RIN * CIN;
#pragma unroll
    for (int i = 0; i < 4; i++) {
        float v = tile[tx][ty + i*8];
        size_t o = ob + (size_t)(x0 + ty + i*8) * RIN + (y0 + tx);
        ot[o] = __float2half_rn(v);
    }
}

// ------------------------------------------------------------------
// fp16 mma.sync grouped GEMM: CTA 128x256, 16 warps (warp tile 64x32),
// BK=64, XOR-swizzled 128B smem rows, ldmatrix.x4, 3-stage cp.async.
// ------------------------------------------------------------------
#define GT 512                   /* threads */
#define STAGE_SZ 49152           /* A 16KB + B 32KB */
#define SMEM_TOTAL (3*STAGE_SZ)  /* 147456 */

template<int KD, int ND, bool PHASE1>
__global__ void __launch_bounds__(GT)
moe_mma_kernel(const float* __restrict__ bias) {
    constexpr int NSLAB = KD / 64;
    const int e   = blockIdx.z;
    const int cnt = g_counts[e];
    const int m0  = blockIdx.y * 128;
    if (m0 >= cnt) return;
    const int off = g_offsets_pad[e];
    const int n0  = blockIdx.x * 256;

    const __half* A  = PHASE1 ? g_a1  : g_a2;
    const __half* Bw = PHASE1 ? g_w1t : g_w2t;

    extern __shared__ char smem[];
    const uint32_t sb = smem_u32(smem);
    const int tid  = threadIdx.x;
    const int wid  = tid >> 5;
    const int lane = tid & 31;
    const int lr   = lane >> 2;      // 0..7
    const int lc   = lane & 3;       // 0..3
    const int warp_m = (wid & 1) * 64;      // 0 / 64
    const int warp_n = (wid >> 1) * 32;     // 0..224

    const size_t arow = (size_t)(off + m0);
    const size_t brow = (size_t)e * ND + n0;

    float acc[4][4][4];
#pragma unroll
    for (int mt = 0; mt < 4; mt++)
#pragma unroll
        for (int nt = 0; nt < 4; nt++)
#pragma unroll
            for (int c = 0; c < 4; c++) acc[mt][nt][c] = 0.f;

    // producer: 3072 16B-chunks per stage (A 1024 + B 2048), 6 per thread
    auto load_stage = [&](int s) {
        const uint32_t stage = sb + (uint32_t)(s % 3) * STAGE_SZ;
        const int k0 = s * 64;
#pragma unroll
        for (int j = 0; j < 6; j++) {
            const int cid = tid + j * GT;           // 0..3071
            if (cid < 1024) {
                const int r = cid >> 3, c = cid & 7;
                const __half* src = A + (arow + r) * KD + k0 + c * 8;
                const uint32_t dst = stage + (uint32_t)r * 128u
                                   + (uint32_t)((c ^ (r & 7)) << 4);
                CP_ASYNC16(dst, src);
            } else {
                const int loc = cid - 1024;
                const int r = loc >> 3, c = loc & 7;
                const __half* src = Bw + (brow + r) * KD + k0 + c * 8;
                const uint32_t dst = stage + 16384u + (uint32_t)r * 128u
                                   + (uint32_t)((c ^ (r & 7)) << 4);
                CP_ASYNC16(dst, src);
            }
        }
        CP_COMMIT();
    };

    load_stage(0);
    if (NSLAB > 1) load_stage(1); else CP_COMMIT();

    // ldmatrix lane-address components (constant across slabs)
    const int a_row_l = warp_m + (lane & 7) + ((lane >> 3) & 1) * 8;  // + mt*16
    const int a_kh    = lane >> 4;                                     // 0/1
    const int b_m     = lane >> 3;                                     // 0..3
    const int b_nt_l  = b_m >> 1;                                      // 0/1 (+p*2)
    const int b_kh    = b_m & 1;
    const int b_row_l = warp_n + (lane & 7) + b_nt_l * 8;              // + p*16

    for (int s = 0; s < NSLAB; s++) {
        if (s + 2 < NSLAB) load_stage(s + 2); else CP_COMMIT();
        CP_WAIT2();
        __syncthreads();

        const uint32_t stage = sb + (uint32_t)(s % 3) * STAGE_SZ;
        const uint32_t sA = stage;
        const uint32_t sB = stage + 16384u;

#pragma unroll
        for (int ks = 0; ks < 4; ks++) {
            uint32_t a[4][4], b[8];
#pragma unroll
            for (int p = 0; p < 2; p++) {
                const int nrow = b_row_l + p * 16;
                const int kch  = ks * 2 + b_kh;
                const uint32_t addr = sB + (uint32_t)nrow * 128u
                                    + (uint32_t)((kch ^ (nrow & 7)) << 4);
                LDSM4(b[p*4+0], b[p*4+1], b[p*4+2], b[p*4+3], addr);
            }
#pragma unroll
            for (int mt = 0; mt < 4; mt++) {
                const int mrow = a_row_l + mt * 16;
                const int kch  = ks * 2 + a_kh;
                const uint32_t addr = sA + (uint32_t)mrow * 128u
                                    + (uint32_t)((kch ^ (mrow & 7)) << 4);
                LDSM4(a[mt][0], a[mt][1], a[mt][2], a[mt][3], addr);
            }
#pragma unroll
            for (int mt = 0; mt < 4; mt++)
#pragma unroll
                for (int nt = 0; nt < 4; nt++)
                    mma_f16(acc[mt][nt][0], acc[mt][nt][1], acc[mt][nt][2], acc[mt][nt][3],
                            a[mt][0], a[mt][1], a[mt][2], a[mt][3],
                            b[nt*2], b[nt*2+1]);
        }
        __syncthreads();
    }

    // ---------------- epilogue (from registers) ----------------
#pragma unroll
    for (int mt = 0; mt < 4; mt++) {
        const size_t r0 = arow + warp_m + mt*16 + lr;
        const size_t r1 = r0 + 8;
#pragma unroll
        for (int nt = 0; nt < 4; nt++) {
            const int col = n0 + warp_n + nt*8 + lc*2;
            if (PHASE1) {
                const float bv0 = bias[(size_t)e * ND + col];
                const float bv1 = bias[(size_t)e * ND + col + 1];
                float v0 = fmaxf(acc[mt][nt][0] + bv0, 0.f);
                float v1 = fmaxf(acc[mt][nt][1] + bv1, 0.f);
                float v2 = fmaxf(acc[mt][nt][2] + bv0, 0.f);
                float v3 = fmaxf(acc[mt][nt][3] + bv1, 0.f);
                __half2 p0 = __floats2half2_rn(v0, v1);
                __half2 p1 = __floats2half2_rn(v2, v3);
                *reinterpret_cast<__half2*>(g_a2 + r0 * H_ + col) = p0;
                *reinterpret_cast<__half2*>(g_a2 + r1 * H_ + col) = p1;
            } else {
                *reinterpret_cast<float2*>(g_eo + r0 * D_ + col) =
                    make_float2(acc[mt][nt][0], acc[mt][nt][1]);
                *reinterpret_cast<float2*>(g_eo + r1 * D_ + col) =
                    make_float2(acc[mt][nt][2], acc[mt][nt][3]);
            }
        }
    }
}

// ------------------------------------------------------------------
// combine: eo(top2) + bias + gates -> momentum -> residual -> LayerNorm
// ------------------------------------------------------------------
__global__ void combine_kernel(const float* __restrict__ x,
                               const float* __restrict__ momentum,
                               const float* __restrict__ b2,
                               const float* __restrict__ ln_g,
                               const float* __restrict__ ln_b,
                               float* __restrict__ out) {
    const int t   = blockIdx.x;
    const int tid = threadIdx.x;
    const int s0 = g_slot[t*2],     s1 = g_slot[t*2+1];
    const float w0 = g_wk[t*2],     w1 = g_wk[t*2+1];
    const int e0 = g_eidx[t*2],     e1 = g_eidx[t*2+1];
    const float* eo0 = g_eo + (size_t)s0 * D_;
    const float* eo1 = g_eo + (size_t)s1 * D_;
    const float* b20 = b2 + (size_t)e0 * D_;
    const float* b21 = b2 + (size_t)e1 * D_;
    const float* xr  = x        + (size_t)t * D_;
    const float* mr  = momentum + (size_t)t * D_;

    float ov[4], nmv[4];
    float sum = 0.f, sumsq = 0.f;
#pragma unroll
    for (int i = 0; i < 4; i++) {
        int d = tid + i * 256;
        float acc = w0 * (eo0[d] + b20[d]) + w1 * (eo1[d] + b21[d]);
        float nm  = -acc + MU_F * mr[d];
        float o   = xr[d] + GAMMA_F * nm;
        nmv[i] = nm; ov[i] = o;
        sum += o; sumsq += o * o;
    }
#pragma unroll
    for (int o = 16; o > 0; o >>= 1) {
        sum   += __shfl_xor_sync(0xffffffffu, sum,   o);
        sumsq += __shfl_xor_sync(0xffffffffu, sumsq, o);
    }
    __shared__ float red[16];
    const int warp = tid >> 5, lane = tid & 31;
    if (lane == 0) { red[warp] = sum; red[8 + warp] = sumsq; }
    __syncthreads();
    float tot = 0.f, totq = 0.f;
#pragma unroll
    for (int wgi = 0; wgi < 8; wgi++) { tot += red[wgi]; totq += red[8 + wgi]; }
    const float mean = tot * (1.f / D_);
    const float var  = totq * (1.f / D_) - mean * mean;
    const float inv  = rsqrtf(var + LN_EPS_F);
#pragma unroll
    for (int i = 0; i < 4; i++) {
        int d = tid + i * 256;
        out[(size_t)t * D_ + d] = (ov[i] - mean) * inv * ln_g[d] + ln_b[d];
        out[(size_t)(NTOK + t) * D_ + d] = nmv[i];
    }
}

// ------------------------------------------------------------------
// launch
// ------------------------------------------------------------------
extern "C" void kernel_launch(void* const* d_in, const int* in_sizes, int n_in,
                              void* d_out, int out_size) {
    const float* x        = (const float*)d_in[0];
    const float* momentum = (const float*)d_in[1];
    const float* Wg       = (const float*)d_in[2];
    const float* bg       = (const float*)d_in[3];
    const float* W1       = (const float*)d_in[4];
    const float* b1       = (const float*)d_in[5];
    const float* W2       = (const float*)d_in[6];
    const float* b2       = (const float*)d_in[7];
    const float* ln_g     = (const float*)d_in[8];
    const float* ln_b     = (const float*)d_in[9];
    float* out            = (float*)d_out;

    cudaFuncSetAttribute(moe_mma_kernel<D_, H_, true>,
                         cudaFuncAttributeMaxDynamicSharedMemorySize, SMEM_TOTAL);
    cudaFuncSetAttribute(moe_mma_kernel<H_, D_, false>,
                         cudaFuncAttributeMaxDynamicSharedMemorySize, SMEM_TOTAL);

    init_kernel<<<(NPAD_MAX + 255) / 256, 256>>>();
    router_kernel<<<NTOK / 8, 256>>>(x, Wg, bg);
    offsets_kernel<<<1, 32>>>();
    scatter_kernel<<<NTOK / 256, 256>>>();
    gather_half_kernel<<<NPAD_MAX, 256>>>(x);

    {   // W1 [e][1024][2048] -> W1t [e][2048][1024] fp16
        dim3 grid(H_ / 32, D_ / 32, E_);
        wtrans_half_kernel<D_, H_, true><<<grid, dim3(32, 8)>>>(W1);
    }
    {   // W2 [e][2048][1024] -> W2t [e][1024][2048] fp16
        dim3 grid(D_ / 32, H_ / 32, E_);
        wtrans_half_kernel<H_, D_, false><<<grid, dim3(32, 8)>>>(W2);
    }

    {   // GEMM1: A1 @ W1t -> relu+bias -> fp16 -> A2
        dim3 grid(H_ / 256, MTILES, E_);
        moe_mma_kernel<D_, H_, true><<<grid, GT, SMEM_TOTAL>>>(b1);
    }
    {   // GEMM2: A2 @ W2t -> g_eo (fp32)
        dim3 grid(D_ / 256, MTILES, E_);
        moe_mma_kernel<H_, D_, false><<<grid, GT, SMEM_TOTAL>>>(nullptr);
    }

    combine_kernel<<<NTOK, 256>>>(x, momentum, b2, ln_g, ln_b, out);
}

// round 11
// speedup vs baseline: 1.1283x; 1.1283x over previous
#include <cuda_runtime.h>
#include <cuda_fp16.h>
#include <math.h>
#include <stdint.h>

#define B_ 4
#define S_ 2048
#define D_ 1024
#define H_ 2048
#define E_ 8
#define NTOK (B_*S_)            /* 8192  */
#define NPAD_MAX 17408          /* 16384 + 8*128 */
#define MTILES (NPAD_MAX/128)   /* 136 */
#define MU_F 0.7f
#define GAMMA_F 1.0f
#define LN_EPS_F 1e-5f

// ------------------------------------------------------------------
// scratch (static __device__; referenced ONLY from device code)
// ------------------------------------------------------------------
__device__ __align__(256) __half g_a1 [(size_t)NPAD_MAX * D_];
__device__ __align__(256) __half g_a2 [(size_t)NPAD_MAX * H_];
__device__ __align__(256) __half g_w1t[(size_t)E_ * H_ * D_];   // [e][h][d]
__device__ __align__(256) __half g_w2t[(size_t)E_ * D_ * H_];   // [e][d][h]
__device__ __align__(256) float  g_eo [(size_t)NPAD_MAX * D_];
__device__ int   g_assign_tok[NPAD_MAX];
__device__ int   g_slot [NTOK * 2];
__device__ float g_wk   [NTOK * 2];
__device__ int   g_eidx [NTOK * 2];
__device__ int   g_counts [E_];
__device__ int   g_offsets_pad[E_];
__device__ int   g_cursor [E_];

// ------------------------------------------------------------------
// PTX helpers
// ------------------------------------------------------------------
__device__ __forceinline__ uint32_t smem_u32(const void* p) {
    uint32_t a;
    asm("{ .reg .u64 t; cvta.to.shared.u64 t, %1; cvt.u32.u64 %0, t; }" : "=r"(a) : "l"(p));
    return a;
}
#define CP_ASYNC16(dst, src) \
    asm volatile("cp.async.cg.shared.global [%0], [%1], 16;" :: "r"(dst), "l"(src) : "memory")
#define CP_COMMIT() asm volatile("cp.async.commit_group;" ::: "memory")
#define CP_WAIT2()  asm volatile("cp.async.wait_group 2;"  ::: "memory")
#define CP_WAIT0()  asm volatile("cp.async.wait_group 0;"  ::: "memory")

#define LDSM4(r0, r1, r2, r3, addr) \
    asm volatile("ldmatrix.sync.aligned.m8n8.x4.shared.b16 {%0,%1,%2,%3}, [%4];" \
                 : "=r"(r0), "=r"(r1), "=r"(r2), "=r"(r3) : "r"(addr))

__device__ __forceinline__ void mma_f16(float& c0, float& c1, float& c2, float& c3,
                                        uint32_t a0, uint32_t a1, uint32_t a2, uint32_t a3,
                                        uint32_t b0, uint32_t b1) {
    asm volatile("mma.sync.aligned.m16n8k16.row.col.f32.f16.f16.f32 "
                 "{%0,%1,%2,%3}, {%4,%5,%6,%7}, {%8,%9}, {%0,%1,%2,%3};"
                 : "+f"(c0), "+f"(c1), "+f"(c2), "+f"(c3)
                 : "r"(a0), "r"(a1), "r"(a2), "r"(a3), "r"(b0), "r"(b1));
}

// ------------------------------------------------------------------
// routing kernels
// ------------------------------------------------------------------
__global__ void init_kernel() {
    int i = blockIdx.x * blockDim.x + threadIdx.x;
    if (i < E_) g_counts[i] = 0;
    if (i < NPAD_MAX) g_assign_tok[i] = -1;
}

__global__ void router_kernel(const float* __restrict__ x,
                              const float* __restrict__ Wg,
                              const float* __restrict__ bg) {
    int gwarp = (blockIdx.x * blockDim.x + threadIdx.x) >> 5;
    int lane  = threadIdx.x & 31;
    if (gwarp >= NTOK) return;
    const float* xr = x + (size_t)gwarp * D_;
    float acc[E_];
#pragma unroll
    for (int e = 0; e < E_; e++) acc[e] = 0.f;
    for (int d = lane; d < D_; d += 32) {
        float xv = xr[d];
        const float4* wr = reinterpret_cast<const float4*>(Wg + (size_t)d * E_);
        float4 w0 = wr[0], w1 = wr[1];
        acc[0] += xv * w0.x; acc[1] += xv * w0.y; acc[2] += xv * w0.z; acc[3] += xv * w0.w;
        acc[4] += xv * w1.x; acc[5] += xv * w1.y; acc[6] += xv * w1.z; acc[7] += xv * w1.w;
    }
#pragma unroll
    for (int e = 0; e < E_; e++)
#pragma unroll
        for (int o = 16; o > 0; o >>= 1)
            acc[e] += __shfl_xor_sync(0xffffffffu, acc[e], o);
    if (lane == 0) {
        float lg[E_];
#pragma unroll
        for (int e = 0; e < E_; e++) lg[e] = acc[e] + bg[e];
        int i0 = 0;
#pragma unroll
        for (int e = 1; e < E_; e++) if (lg[e] > lg[i0]) i0 = e;
        int i1 = -1;
#pragma unroll
        for (int e = 0; e < E_; e++) {
            if (e == i0) continue;
            if (i1 < 0 || lg[e] > lg[i1]) i1 = e;
        }
        float e1 = __expf(lg[i1] - lg[i0]);
        float inv = 1.f / (1.f + e1);
        g_eidx[gwarp*2]   = i0;  g_eidx[gwarp*2+1] = i1;
        g_wk  [gwarp*2]   = inv; g_wk  [gwarp*2+1] = e1 * inv;
        atomicAdd(&g_counts[i0], 1);
        atomicAdd(&g_counts[i1], 1);
    }
}

__global__ void offsets_kernel() {
    if (threadIdx.x == 0) {
        int acc = 0;
        for (int e = 0; e < E_; e++) {
            g_offsets_pad[e] = acc;
            g_cursor[e]      = acc;
            acc += (g_counts[e] + 127) & ~127;
        }
    }
}

__global__ void scatter_kernel() {
    int t = blockIdx.x * blockDim.x + threadIdx.x;
    if (t >= NTOK) return;
#pragma unroll
    for (int k = 0; k < 2; k++) {
        int e = g_eidx[t*2 + k];
        int pos = atomicAdd(&g_cursor[e], 1);
        g_assign_tok[pos] = t;
        g_slot[t*2 + k] = pos;
    }
}

// gather x rows into padded fp16 A1 (zeros for pad rows)
__global__ void gather_half_kernel(const float* __restrict__ x) {
    int slot = blockIdx.x;
    int t = g_assign_tok[slot];
    int d4 = threadIdx.x;                // 256 threads x 4 elems = 1024
    uint2 pk = make_uint2(0u, 0u);
    if (t >= 0) {
        float4 v = reinterpret_cast<const float4*>(x + (size_t)t * D_)[d4];
        __half2 p0 = __floats2half2_rn(v.x, v.y);
        __half2 p1 = __floats2half2_rn(v.z, v.w);
        pk.x = *reinterpret_cast<uint32_t*>(&p0);
        pk.y = *reinterpret_cast<uint32_t*>(&p1);
    }
    reinterpret_cast<uint2*>(g_a1 + (size_t)slot * D_)[d4] = pk;
}

// transpose + fp16 weights: in [e][RIN][CIN] -> out [e][CIN][RIN]
template<int RIN, int CIN, bool W1SEL>
__global__ void wtrans_half_kernel(const float* __restrict__ W) {
    __shared__ float tile[32][33];
    int e = blockIdx.z;
    int x0 = blockIdx.x * 32, y0 = blockIdx.y * 32;
    int tx = threadIdx.x, ty = threadIdx.y;  // 32 x 8
    const float* in = W + (size_t)e * RIN * CIN;
#pragma unroll
    for (int i = 0; i < 4; i++)
        tile[ty + i*8][tx] = in[(size_t)(y0 + ty + i*8) * CIN + x0 + tx];
    __syncthreads();
    __half* ot = W1SEL ? g_w1t : g_w2t;
    size_t ob = (size_t)e * RIN * CIN;
#pragma unroll
    for (int i = 0; i < 4; i++) {
        float v = tile[tx][ty + i*8];
        size_t o = ob + (size_t)(x0 + ty + i*8) * RIN + (y0 + tx);
        ot[o] = __float2half_rn(v);
    }
}

// ------------------------------------------------------------------
// fp16 mma.sync grouped GEMM: CTA 128x128, 8 warps (warp tile 64x32),
// BK=64, XOR-swizzled 128B smem rows, ldmatrix.x4, 3-stage cp.async.
// __launch_bounds__(256,2) pins regs <=128 so 2 CTAs/SM co-reside
// (two independent barrier domains — load-bearing, see R10 regression).
// ------------------------------------------------------------------
#define STAGE_SZ 32768           /* A 16KB + B 16KB */
#define SMEM_TOTAL (3*STAGE_SZ)  /* 98304; x2 CTAs = 192KB <= 228KB */

template<int KD, int ND, bool PHASE1>
__global__ void __launch_bounds__(256, 2)
moe_mma_kernel(const float* __restrict__ bias) {
    constexpr int NSLAB = KD / 64;
    const int e   = blockIdx.z;
    const int cnt = g_counts[e];
    const int m0  = blockIdx.y * 128;
    if (m0 >= cnt) return;
    const int off = g_offsets_pad[e];
    const int n0  = blockIdx.x * 128;

    const __half* A  = PHASE1 ? g_a1  : g_a2;
    const __half* Bw = PHASE1 ? g_w1t : g_w2t;

    extern __shared__ char smem[];
    const uint32_t sb = smem_u32(smem);
    const int tid  = threadIdx.x;
    const int wid  = tid >> 5;
    const int lane = tid & 31;
    const int lr   = lane >> 2;      // 0..7
    const int lc   = lane & 3;       // 0..3
    const int warp_m = (wid & 1) * 64;
    const int warp_n = (wid >> 1) * 32;

    const size_t arow = (size_t)(off + m0);
    const size_t brow = (size_t)e * ND + n0;

    float acc[4][4][4];
#pragma unroll
    for (int mt = 0; mt < 4; mt++)
#pragma unroll
        for (int nt = 0; nt < 4; nt++)
#pragma unroll
            for (int c = 0; c < 4; c++) acc[mt][nt][c] = 0.f;

    // producer: 2048 16B-chunks per stage (A 1024 + B 1024), 8 per thread
    auto load_stage = [&](int s) {
        const uint32_t stage = sb + (uint32_t)(s % 3) * STAGE_SZ;
        const int k0 = s * 64;
#pragma unroll
        for (int j = 0; j < 8; j++) {
            const int cid = tid + j * 256;          // 0..2047
            const int op  = cid >> 10;              // 0:A 1:B
            const int loc = cid & 1023;
            const int r   = loc >> 3;               // 0..127
            const int c   = loc & 7;                // 16B chunk within 128B row
            const __half* src = (op == 0)
                ? (A  + (arow + r) * KD + k0 + c * 8)
                : (Bw + (brow + r) * KD + k0 + c * 8);
            const uint32_t dst = stage + (uint32_t)op * 16384u
                               + (uint32_t)r * 128u + (uint32_t)((c ^ (r & 7)) << 4);
            CP_ASYNC16(dst, src);
        }
        CP_COMMIT();
    };

    load_stage(0);
    if (NSLAB > 1) load_stage(1); else CP_COMMIT();

    // ldmatrix lane-address components (constant across slabs)
    const int a_row_l = warp_m + (lane & 7) + ((lane >> 3) & 1) * 8;  // + mt*16
    const int a_kh    = lane >> 4;                                     // 0/1
    const int b_m     = lane >> 3;                                     // 0..3
    const int b_nt_l  = b_m >> 1;                                      // 0/1 (+p*2)
    const int b_kh    = b_m & 1;
    const int b_row_l = warp_n + (lane & 7) + b_nt_l * 8;              // + p*16

    for (int s = 0; s < NSLAB; s++) {
        if (s + 2 < NSLAB) load_stage(s + 2); else CP_COMMIT();
        CP_WAIT2();
        __syncthreads();

        const uint32_t stage = sb + (uint32_t)(s % 3) * STAGE_SZ;
        const uint32_t sA = stage;
        const uint32_t sB = stage + 16384u;

#pragma unroll
        for (int ks = 0; ks < 4; ks++) {
            uint32_t a[4][4], b[8];
#pragma unroll
            for (int p = 0; p < 2; p++) {
                const int nrow = b_row_l + p * 16;
                const int kch  = ks * 2 + b_kh;
                const uint32_t addr = sB + (uint32_t)nrow * 128u
                                    + (uint32_t)((kch ^ (nrow & 7)) << 4);
                LDSM4(b[p*4+0], b[p*4+1], b[p*4+2], b[p*4+3], addr);
            }
#pragma unroll
            for (int mt = 0; mt < 4; mt++) {
                const int mrow = a_row_l + mt * 16;
                const int kch  = ks * 2 + a_kh;
                const uint32_t addr = sA + (uint32_t)mrow * 128u
                                    + (uint32_t)((kch ^ (mrow & 7)) << 4);
                LDSM4(a[mt][0], a[mt][1], a[mt][2], a[mt][3], addr);
            }
#pragma unroll
            for (int mt = 0; mt < 4; mt++)
#pragma unroll
                for (int nt = 0; nt < 4; nt++)
                    mma_f16(acc[mt][nt][0], acc[mt][nt][1], acc[mt][nt][2], acc[mt][nt][3],
                            a[mt][0], a[mt][1], a[mt][2], a[mt][3],
                            b[nt*2], b[nt*2+1]);
        }
        __syncthreads();
    }

    // ---------------- epilogue (from registers) ----------------
#pragma unroll
    for (int mt = 0; mt < 4; mt++) {
        const size_t r0 = arow + warp_m + mt*16 + lr;
        const size_t r1 = r0 + 8;
#pragma unroll
        for (int nt = 0; nt < 4; nt++) {
            const int col = n0 + warp_n + nt*8 + lc*2;
            if (PHASE1) {
                const float bv0 = bias[(size_t)e * ND + col];
                const float bv1 = bias[(size_t)e * ND + col + 1];
                float v0 = fmaxf(acc[mt][nt][0] + bv0, 0.f);
                float v1 = fmaxf(acc[mt][nt][1] + bv1, 0.f);
                float v2 = fmaxf(acc[mt][nt][2] + bv0, 0.f);
                float v3 = fmaxf(acc[mt][nt][3] + bv1, 0.f);
                __half2 p0 = __floats2half2_rn(v0, v1);
                __half2 p1 = __floats2half2_rn(v2, v3);
                *reinterpret_cast<__half2*>(g_a2 + r0 * H_ + col) = p0;
                *reinterpret_cast<__half2*>(g_a2 + r1 * H_ + col) = p1;
            } else {
                *reinterpret_cast<float2*>(g_eo + r0 * D_ + col) =
                    make_float2(acc[mt][nt][0], acc[mt][nt][1]);
                *reinterpret_cast<float2*>(g_eo + r1 * D_ + col) =
                    make_float2(acc[mt][nt][2], acc[mt][nt][3]);
            }
        }
    }
}

// ------------------------------------------------------------------
// combine: eo(top2) + bias + gates -> momentum -> residual -> LayerNorm
// ------------------------------------------------------------------
__global__ void combine_kernel(const float* __restrict__ x,
                               const float* __restrict__ momentum,
                               const float* __restrict__ b2,
                               const float* __restrict__ ln_g,
                               const float* __restrict__ ln_b,
                               float* __restrict__ out) {
    const int t   = blockIdx.x;
    const int tid = threadIdx.x;
    const int s0 = g_slot[t*2],     s1 = g_slot[t*2+1];
    const float w0 = g_wk[t*2],     w1 = g_wk[t*2+1];
    const int e0 = g_eidx[t*2],     e1 = g_eidx[t*2+1];
    const float* eo0 = g_eo + (size_t)s0 * D_;
    const float* eo1 = g_eo + (size_t)s1 * D_;
    const float* b20 = b2 + (size_t)e0 * D_;
    const float* b21 = b2 + (size_t)e1 * D_;
    const float* xr  = x        + (size_t)t * D_;
    const float* mr  = momentum + (size_t)t * D_;

    float ov[4], nmv[4];
    float sum = 0.f, sumsq = 0.f;
#pragma unroll
    for (int i = 0; i < 4; i++) {
        int d = tid + i * 256;
        float acc = w0 * (eo0[d] + b20[d]) + w1 * (eo1[d] + b21[d]);
        float nm  = -acc + MU_F * mr[d];
        float o   = xr[d] + GAMMA_F * nm;
        nmv[i] = nm; ov[i] = o;
        sum += o; sumsq += o * o;
    }
#pragma unroll
    for (int o = 16; o > 0; o >>= 1) {
        sum   += __shfl_xor_sync(0xffffffffu, sum,   o);
        sumsq += __shfl_xor_sync(0xffffffffu, sumsq, o);
    }
    __shared__ float red[16];
    const int warp = tid >> 5, lane = tid & 31;
    if (lane == 0) { red[warp] = sum; red[8 + warp] = sumsq; }
    __syncthreads();
    float tot = 0.f, totq = 0.f;
#pragma unroll
    for (int wgi = 0; wgi < 8; wgi++) { tot += red[wgi]; totq += red[8 + wgi]; }
    const float mean = tot * (1.f / D_);
    const float var  = totq * (1.f / D_) - mean * mean;
    const float inv  = rsqrtf(var + LN_EPS_F);
#pragma unroll
    for (int i = 0; i < 4; i++) {
        int d = tid + i * 256;
        out[(size_t)t * D_ + d] = (ov[i] - mean) * inv * ln_g[d] + ln_b[d];
        out[(size_t)(NTOK + t) * D_ + d] = nmv[i];
    }
}

// ------------------------------------------------------------------
// launch
// ------------------------------------------------------------------
extern "C" void kernel_launch(void* const* d_in, const int* in_sizes, int n_in,
                              void* d_out, int out_size) {
    const float* x        = (const float*)d_in[0];
    const float* momentum = (const float*)d_in[1];
    const float* Wg       = (const float*)d_in[2];
    const float* bg       = (const float*)d_in[3];
    const float* W1       = (const float*)d_in[4];
    const float* b1       = (const float*)d_in[5];
    const float* W2       = (const float*)d_in[6];
    const float* b2       = (const float*)d_in[7];
    const float* ln_g     = (const float*)d_in[8];
    const float* ln_b     = (const float*)d_in[9];
    float* out            = (float*)d_out;

    cudaFuncSetAttribute(moe_mma_kernel<D_, H_, true>,
                         cudaFuncAttributeMaxDynamicSharedMemorySize, SMEM_TOTAL);
    cudaFuncSetAttribute(moe_mma_kernel<H_, D_, false>,
                         cudaFuncAttributeMaxDynamicSharedMemorySize, SMEM_TOTAL);

    init_kernel<<<(NPAD_MAX + 255) / 256, 256>>>();
    router_kernel<<<NTOK / 8, 256>>>(x, Wg, bg);
    offsets_kernel<<<1, 32>>>();
    scatter_kernel<<<NTOK / 256, 256>>>();
    gather_half_kernel<<<NPAD_MAX, 256>>>(x);

    {   // W1 [e][1024][2048] -> W1t [e][2048][1024] fp16
        dim3 grid(H_ / 32, D_ / 32, E_);
        wtrans_half_kernel<D_, H_, true><<<grid, dim3(32, 8)>>>(W1);
    }
    {   // W2 [e][2048][1024] -> W2t [e][1024][2048] fp16
        dim3 grid(D_ / 32, H_ / 32, E_);
        wtrans_half_kernel<H_, D_, false><<<grid, dim3(32, 8)>>>(W2);
    }

    {   // GEMM1: A1 @ W1t -> relu+bias -> fp16 -> A2
        dim3 grid(H_ / 128, MTILES, E_);
        moe_mma_kernel<D_, H_, true><<<grid, 256, SMEM_TOTAL>>>(b1);
    }
    {   // GEMM2: A2 @ W2t -> g_eo (fp32)
        dim3 grid(D_ / 128, MTILES, E_);
        moe_mma_kernel<H_, D_, false><<<grid, 256, SMEM_TOTAL>>>(nullptr);
    }

    combine_kernel<<<NTOK, 256>>>(x, momentum, b2, ln_g, ln_b, out);
}

// round 12
// speedup vs baseline: 1.1635x; 1.0313x over previous
#include <cuda_runtime.h>
#include <cuda_fp16.h>
#include <math.h>
#include <stdint.h>

#define B_ 4
#define S_ 2048
#define D_ 1024
#define H_ 2048
#define E_ 8
#define NTOK (B_*S_)            /* 8192  */
#define NPAD_MAX 17408          /* 16384 + 8*128 */
#define MTILES (NPAD_MAX/128)   /* 136 */
#define MU_F 0.7f
#define GAMMA_F 1.0f
#define LN_EPS_F 1e-5f
#define WELEMS (E_*D_*H_)       /* 16.78M per weight tensor */
#define CONV_BLOCKS (WELEMS/1024)  /* 16384 blocks per tensor, 256 thr x 4 elems */

// ------------------------------------------------------------------
// scratch (static __device__; referenced ONLY from device code)
// ------------------------------------------------------------------
__device__ __align__(256) __half g_a1 [(size_t)NPAD_MAX * D_];
__device__ __align__(256) __half g_a2 [(size_t)NPAD_MAX * H_];
__device__ __align__(256) __half g_w1h[(size_t)WELEMS];   // fp16 W1, same [e][d][h] layout
__device__ __align__(256) __half g_w2h[(size_t)WELEMS];   // fp16 W2, same [e][h][d] layout
__device__ __align__(256) float  g_eo [(size_t)NPAD_MAX * D_];
__device__ int   g_assign_tok[NPAD_MAX];
__device__ int   g_slot [NTOK * 2];
__device__ float g_wk   [NTOK * 2];
__device__ int   g_eidx [NTOK * 2];
__device__ int   g_counts [E_];
__device__ int   g_offsets_pad[E_];
__device__ int   g_cursor [E_];

// ------------------------------------------------------------------
// PTX helpers
// ------------------------------------------------------------------
__device__ __forceinline__ uint32_t smem_u32(const void* p) {
    uint32_t a;
    asm("{ .reg .u64 t; cvta.to.shared.u64 t, %1; cvt.u32.u64 %0, t; }" : "=r"(a) : "l"(p));
    return a;
}
#define CP_ASYNC16(dst, src) \
    asm volatile("cp.async.cg.shared.global [%0], [%1], 16;" :: "r"(dst), "l"(src) : "memory")
#define CP_COMMIT() asm volatile("cp.async.commit_group;" ::: "memory")
#define CP_WAIT2()  asm volatile("cp.async.wait_group 2;"  ::: "memory")

#define LDSM4(r0, r1, r2, r3, addr) \
    asm volatile("ldmatrix.sync.aligned.m8n8.x4.shared.b16 {%0,%1,%2,%3}, [%4];" \
                 : "=r"(r0), "=r"(r1), "=r"(r2), "=r"(r3) : "r"(addr))
#define LDSM4T(r0, r1, r2, r3, addr) \
    asm volatile("ldmatrix.sync.aligned.m8n8.x4.trans.shared.b16 {%0,%1,%2,%3}, [%4];" \
                 : "=r"(r0), "=r"(r1), "=r"(r2), "=r"(r3) : "r"(addr))

__device__ __forceinline__ void mma_f16(float& c0, float& c1, float& c2, float& c3,
                                        uint32_t a0, uint32_t a1, uint32_t a2, uint32_t a3,
                                        uint32_t b0, uint32_t b1) {
    asm volatile("mma.sync.aligned.m16n8k16.row.col.f32.f16.f16.f32 "
                 "{%0,%1,%2,%3}, {%4,%5,%6,%7}, {%8,%9}, {%0,%1,%2,%3};"
                 : "+f"(c0), "+f"(c1), "+f"(c2), "+f"(c3)
                 : "r"(a0), "r"(a1), "r"(a2), "r"(a3), "r"(b0), "r"(b1));
}

// ------------------------------------------------------------------
// routing kernels
// ------------------------------------------------------------------
__global__ void router_kernel(const float* __restrict__ x,
                              const float* __restrict__ Wg,
                              const float* __restrict__ bg) {
    int gwarp = (blockIdx.x * blockDim.x + threadIdx.x) >> 5;
    int lane  = threadIdx.x & 31;
    if (gwarp >= NTOK) return;
    const float* xr = x + (size_t)gwarp * D_;
    float acc[E_];
#pragma unroll
    for (int e = 0; e < E_; e++) acc[e] = 0.f;
    for (int d = lane; d < D_; d += 32) {
        float xv = xr[d];
        const float4* wr = reinterpret_cast<const float4*>(Wg + (size_t)d * E_);
        float4 w0 = wr[0], w1 = wr[1];
        acc[0] += xv * w0.x; acc[1] += xv * w0.y; acc[2] += xv * w0.z; acc[3] += xv * w0.w;
        acc[4] += xv * w1.x; acc[5] += xv * w1.y; acc[6] += xv * w1.z; acc[7] += xv * w1.w;
    }
#pragma unroll
    for (int e = 0; e < E_; e++)
#pragma unroll
        for (int o = 16; o > 0; o >>= 1)
            acc[e] += __shfl_xor_sync(0xffffffffu, acc[e], o);
    if (lane == 0) {
        float lg[E_];
#pragma unroll
        for (int e = 0; e < E_; e++) lg[e] = acc[e] + bg[e];
        int i0 = 0;
#pragma unroll
        for (int e = 1; e < E_; e++) if (lg[e] > lg[i0]) i0 = e;
        int i1 = -1;
#pragma unroll
        for (int e = 0; e < E_; e++) {
            if (e == i0) continue;
            if (i1 < 0 || lg[e] > lg[i1]) i1 = e;
        }
        float e1 = __expf(lg[i1] - lg[i0]);
        float inv = 1.f / (1.f + e1);
        g_eidx[gwarp*2]   = i0;  g_eidx[gwarp*2+1] = i1;
        g_wk  [gwarp*2]   = inv; g_wk  [gwarp*2+1] = e1 * inv;
    }
}

// single block: count experts, compute padded offsets, init cursors
__global__ void countoffs_kernel() {
    __shared__ int scnt[E_];
    const int tid = threadIdx.x;
    if (tid < E_) scnt[tid] = 0;
    __syncthreads();
    int local[E_];
#pragma unroll
    for (int e = 0; e < E_; e++) local[e] = 0;
    for (int i = tid; i < NTOK * 2; i += 256) {
        int v = g_eidx[i];
#pragma unroll
        for (int e = 0; e < E_; e++) local[e] += (v == e) ? 1 : 0;
    }
#pragma unroll
    for (int e = 0; e < E_; e++)
        if (local[e]) atomicAdd(&scnt[e], local[e]);
    __syncthreads();
    if (tid == 0) {
        int acc = 0;
        for (int e = 0; e < E_; e++) {
            g_counts[e]      = scnt[e];
            g_offsets_pad[e] = acc;
            g_cursor[e]      = acc;
            acc += (scnt[e] + 127) & ~127;
        }
    }
}

__global__ void scatter_kernel() {
    int t = blockIdx.x * blockDim.x + threadIdx.x;
    if (t >= NTOK) return;
#pragma unroll
    for (int k = 0; k < 2; k++) {
        int e = g_eidx[t*2 + k];
        int pos = atomicAdd(&g_cursor[e], 1);
        g_assign_tok[pos] = t;
        g_slot[t*2 + k] = pos;
    }
}

// fused prep: blocks [0, NPAD_MAX) gather x rows -> fp16 A1 (zero pads);
//             blocks [NPAD_MAX, +CONV) convert W1 fp32->fp16;
//             blocks [.., +CONV)       convert W2 fp32->fp16.
__global__ void prep_kernel(const float* __restrict__ x,
                            const float* __restrict__ W1,
                            const float* __restrict__ W2) {
    const int b = blockIdx.x;
    const int tid = threadIdx.x;
    if (b < NPAD_MAX) {
        const int slot = b;
        int e = 0;
#pragma unroll
        for (int k = 1; k < E_; k++) if (slot >= g_offsets_pad[k]) e = k;
        const bool pad = (slot - g_offsets_pad[e]) >= g_counts[e];
        uint2 pk = make_uint2(0u, 0u);
        if (!pad) {
            const int t = g_assign_tok[slot];
            float4 v = reinterpret_cast<const float4*>(x + (size_t)t * D_)[tid];
            __half2 p0 = __floats2half2_rn(v.x, v.y);
            __half2 p1 = __floats2half2_rn(v.z, v.w);
            pk.x = *reinterpret_cast<uint32_t*>(&p0);
            pk.y = *reinterpret_cast<uint32_t*>(&p1);
        }
        reinterpret_cast<uint2*>(g_a1 + (size_t)slot * D_)[tid] = pk;
    } else {
        const int cb = b - NPAD_MAX;
        const bool w2 = (cb >= CONV_BLOCKS);
        const int cbb = w2 ? (cb - CONV_BLOCKS) : cb;
        const float* src = w2 ? W2 : W1;
        __half* dst = w2 ? g_w2h : g_w1h;
        const size_t i4 = (size_t)cbb * 256 + tid;   // float4 index
        float4 v = reinterpret_cast<const float4*>(src)[i4];
        __half2 p0 = __floats2half2_rn(v.x, v.y);
        __half2 p1 = __floats2half2_rn(v.z, v.w);
        uint2 pk;
        pk.x = *reinterpret_cast<uint32_t*>(&p0);
        pk.y = *reinterpret_cast<uint32_t*>(&p1);
        reinterpret_cast<uint2*>(dst)[i4] = pk;
    }
}

// ------------------------------------------------------------------
// fp16 mma.sync grouped GEMM: CTA 128x128, 8 warps (warp tile 64x32),
// BK=64, 3-stage cp.async, __launch_bounds__(256,2) => 2 CTAs/SM.
// A: m-major rows 128B, swizzle c^(r&7), LDSM non-trans.
// B: K-MAJOR rows 256B (64 k-rows x 128 n), swizzle c^(r&15), LDSM.trans —
//    feeds straight from the un-transposed fp16 weight copy.
// ------------------------------------------------------------------
#define STAGE_SZ 32768           /* A 16KB + B 16KB */
#define SMEM_TOTAL (3*STAGE_SZ)  /* 98304; x2 CTAs = 192KB <= 228KB */

template<int KD, int ND, bool PHASE1>
__global__ void __launch_bounds__(256, 2)
moe_mma_kernel(const float* __restrict__ bias) {
    constexpr int NSLAB = KD / 64;
    const int e   = blockIdx.z;
    const int cnt = g_counts[e];
    const int m0  = blockIdx.y * 128;
    if (m0 >= cnt) return;
    const int off = g_offsets_pad[e];
    const int n0  = blockIdx.x * 128;

    const __half* A  = PHASE1 ? g_a1  : g_a2;
    const __half* Bw = PHASE1 ? g_w1h : g_w2h;

    extern __shared__ char smem[];
    const uint32_t sb = smem_u32(smem);
    const int tid  = threadIdx.x;
    const int wid  = tid >> 5;
    const int lane = tid & 31;
    const int lr   = lane >> 2;      // 0..7
    const int lc   = lane & 3;       // 0..3
    const int warp_m = (wid & 1) * 64;
    const int warp_n = (wid >> 1) * 32;

    const size_t arow = (size_t)(off + m0);
    const __half* Bb = Bw + (size_t)e * KD * ND + n0;   // row k: +k*ND

    float acc[4][4][4];
#pragma unroll
    for (int mt = 0; mt < 4; mt++)
#pragma unroll
        for (int nt = 0; nt < 4; nt++)
#pragma unroll
            for (int c = 0; c < 4; c++) acc[mt][nt][c] = 0.f;

    // producer: A 1024 chunks (128 rows x 8), B 1024 chunks (64 rows x 16)
    auto load_stage = [&](int s) {
        const uint32_t stage = sb + (uint32_t)(s % 3) * STAGE_SZ;
        const int k0 = s * 64;
#pragma unroll
        for (int j = 0; j < 8; j++) {
            const int cid = tid + j * 256;          // 0..2047
            if (cid < 1024) {
                const int r = cid >> 3, c = cid & 7;
                const __half* src = A + (arow + r) * KD + k0 + c * 8;
                const uint32_t dst = stage + (uint32_t)r * 128u
                                   + (uint32_t)((c ^ (r & 7)) << 4);
                CP_ASYNC16(dst, src);
            } else {
                const int loc = cid - 1024;
                const int r = loc >> 4, c = loc & 15;     // k-row, n-chunk
                const __half* src = Bb + (size_t)(k0 + r) * ND + c * 8;
                const uint32_t dst = stage + 16384u + (uint32_t)r * 256u
                                   + (uint32_t)((c ^ (r & 15)) << 4);
                CP_ASYNC16(dst, src);
            }
        }
        CP_COMMIT();
    };

    load_stage(0);
    if (NSLAB > 1) load_stage(1); else CP_COMMIT();

    // ldmatrix lane-address components (constant across slabs)
    const int a_row_l = warp_m + (lane & 7) + ((lane >> 3) & 1) * 8;  // + mt*16
    const int a_kh    = lane >> 4;                                     // 0/1
    const int b_m     = lane >> 3;                                     // 0..3
    const int b_nt_l  = b_m >> 1;                                      // 0/1
    const int b_kh    = b_m & 1;                                       // k8 half
    const int b_r15   = b_kh * 8 + (lane & 7);                         // row & 15
    const int b_cb    = (warp_n >> 3) + b_nt_l;                        // + p*2

    for (int s = 0; s < NSLAB; s++) {
        if (s + 2 < NSLAB) load_stage(s + 2); else CP_COMMIT();
        CP_WAIT2();
        __syncthreads();

        const uint32_t stage = sb + (uint32_t)(s % 3) * STAGE_SZ;
        const uint32_t sA = stage;
        const uint32_t sB = stage + 16384u;

#pragma unroll
        for (int ks = 0; ks < 4; ks++) {
            uint32_t a[4][4], b[8];
            // B fragments via ldmatrix.trans from K-major tile
#pragma unroll
            for (int p = 0; p < 2; p++) {
                const int krow = ks * 16 + b_r15;                 // 0..63
                const int cch  = (b_cb + p * 2) ^ b_r15;          // swizzled chunk
                const uint32_t addr = sB + (uint32_t)krow * 256u
                                    + (uint32_t)(cch << 4);
                LDSM4T(b[p*4+0], b[p*4+1], b[p*4+2], b[p*4+3], addr);
            }
            // A fragments (unchanged)
#pragma unroll
            for (int mt = 0; mt < 4; mt++) {
                const int mrow = a_row_l + mt * 16;
                const int kch  = ks * 2 + a_kh;
                const uint32_t addr = sA + (uint32_t)mrow * 128u
                                    + (uint32_t)((kch ^ (mrow & 7)) << 4);
                LDSM4(a[mt][0], a[mt][1], a[mt][2], a[mt][3], addr);
            }
#pragma unroll
            for (int mt = 0; mt < 4; mt++)
#pragma unroll
                for (int nt = 0; nt < 4; nt++)
                    mma_f16(acc[mt][nt][0], acc[mt][nt][1], acc[mt][nt][2], acc[mt][nt][3],
                            a[mt][0], a[mt][1], a[mt][2], a[mt][3],
                            b[nt*2], b[nt*2+1]);
        }
        __syncthreads();
    }

    // ---------------- epilogue (from registers) ----------------
#pragma unroll
    for (int mt = 0; mt < 4; mt++) {
        const size_t r0 = arow + warp_m + mt*16 + lr;
        const size_t r1 = r0 + 8;
#pragma unroll
        for (int nt = 0; nt < 4; nt++) {
            const int col = n0 + warp_n + nt*8 + lc*2;
            if (PHASE1) {
                const float bv0 = bias[(size_t)e * ND + col];
                const float bv1 = bias[(size_t)e * ND + col + 1];
                float v0 = fmaxf(acc[mt][nt][0] + bv0, 0.f);
                float v1 = fmaxf(acc[mt][nt][1] + bv1, 0.f);
                float v2 = fmaxf(acc[mt][nt][2] + bv0, 0.f);
                float v3 = fmaxf(acc[mt][nt][3] + bv1, 0.f);
                __half2 p0 = __floats2half2_rn(v0, v1);
                __half2 p1 = __floats2half2_rn(v2, v3);
                *reinterpret_cast<__half2*>(g_a2 + r0 * H_ + col) = p0;
                *reinterpret_cast<__half2*>(g_a2 + r1 * H_ + col) = p1;
            } else {
                *reinterpret_cast<float2*>(g_eo + r0 * D_ + col) =
                    make_float2(acc[mt][nt][0], acc[mt][nt][1]);
                *reinterpret_cast<float2*>(g_eo + r1 * D_ + col) =
                    make_float2(acc[mt][nt][2], acc[mt][nt][3]);
            }
        }
    }
}

// ------------------------------------------------------------------
// combine: eo(top2) + bias + gates -> momentum -> residual -> LayerNorm
// ------------------------------------------------------------------
__global__ void combine_kernel(const float* __restrict__ x,
                               const float* __restrict__ momentum,
                               const float* __restrict__ b2,
                               const float* __restrict__ ln_g,
                               const float* __restrict__ ln_b,
                               float* __restrict__ out) {
    const int t   = blockIdx.x;
    const int tid = threadIdx.x;
    const int s0 = g_slot[t*2],     s1 = g_slot[t*2+1];
    const float w0 = g_wk[t*2],     w1 = g_wk[t*2+1];
    const int e0 = g_eidx[t*2],     e1 = g_eidx[t*2+1];
    const float* eo0 = g_eo + (size_t)s0 * D_;
    const float* eo1 = g_eo + (size_t)s1 * D_;
    const float* b20 = b2 + (size_t)e0 * D_;
    const float* b21 = b2 + (size_t)e1 * D_;
    const float* xr  = x        + (size_t)t * D_;
    const float* mr  = momentum + (size_t)t * D_;

    float ov[4], nmv[4];
    float sum = 0.f, sumsq = 0.f;
#pragma unroll
    for (int i = 0; i < 4; i++) {
        int d = tid + i * 256;
        float acc = w0 * (eo0[d] + b20[d]) + w1 * (eo1[d] + b21[d]);
        float nm  = -acc + MU_F * mr[d];
        float o   = xr[d] + GAMMA_F * nm;
        nmv[i] = nm; ov[i] = o;
        sum += o; sumsq += o * o;
    }
#pragma unroll
    for (int o = 16; o > 0; o >>= 1) {
        sum   += __shfl_xor_sync(0xffffffffu, sum,   o);
        sumsq += __shfl_xor_sync(0xffffffffu, sumsq, o);
    }
    __shared__ float red[16];
    const int warp = tid >> 5, lane = tid & 31;
    if (lane == 0) { red[warp] = sum; red[8 + warp] = sumsq; }
    __syncthreads();
    float tot = 0.f, totq = 0.f;
#pragma unroll
    for (int wgi = 0; wgi < 8; wgi++) { tot += red[wgi]; totq += red[8 + wgi]; }
    const float mean = tot * (1.f / D_);
    const float var  = totq * (1.f / D_) - mean * mean;
    const float inv  = rsqrtf(var + LN_EPS_F);
#pragma unroll
    for (int i = 0; i < 4; i++) {
        int d = tid + i * 256;
        out[(size_t)t * D_ + d] = (ov[i] - mean) * inv * ln_g[d] + ln_b[d];
        out[(size_t)(NTOK + t) * D_ + d] = nmv[i];
    }
}

// ------------------------------------------------------------------
// launch
// ------------------------------------------------------------------
extern "C" void kernel_launch(void* const* d_in, const int* in_sizes, int n_in,
                              void* d_out, int out_size) {
    const float* x        = (const float*)d_in[0];
    const float* momentum = (const float*)d_in[1];
    const float* Wg       = (const float*)d_in[2];
    const float* bg       = (const float*)d_in[3];
    const float* W1       = (const float*)d_in[4];
    const float* b1       = (const float*)d_in[5];
    const float* W2       = (const float*)d_in[6];
    const float* b2       = (const float*)d_in[7];
    const float* ln_g     = (const float*)d_in[8];
    const float* ln_b     = (const float*)d_in[9];
    float* out            = (float*)d_out;

    cudaFuncSetAttribute(moe_mma_kernel<D_, H_, true>,
                         cudaFuncAttributeMaxDynamicSharedMemorySize, SMEM_TOTAL);
    cudaFuncSetAttribute(moe_mma_kernel<H_, D_, false>,
                         cudaFuncAttributeMaxDynamicSharedMemorySize, SMEM_TOTAL);

    router_kernel<<<NTOK / 8, 256>>>(x, Wg, bg);
    countoffs_kernel<<<1, 256>>>();
    scatter_kernel<<<NTOK / 256, 256>>>();
    prep_kernel<<<NPAD_MAX + 2 * CONV_BLOCKS, 256>>>(x, W1, W2);

    {   // GEMM1: A1 @ W1 (K-major B) -> relu+bias -> fp16 -> A2
        dim3 grid(H_ / 128, MTILES, E_);
        moe_mma_kernel<D_, H_, true><<<grid, 256, SMEM_TOTAL>>>(b1);
    }
    {   // GEMM2: A2 @ W2 (K-major B) -> g_eo (fp32)
        dim3 grid(D_ / 128, MTILES, E_);
        moe_mma_kernel<H_, D_, false><<<grid, 256, SMEM_TOTAL>>>(nullptr);
    }

    combine_kernel<<<NTOK, 256>>>(x, momentum, b2, ln_g, ln_b, out);
}

// round 14
// speedup vs baseline: 1.1735x; 1.0085x over previous
#include <cuda_runtime.h>
#include <cuda_fp16.h>
#include <math.h>
#include <stdint.h>

#define B_ 4
#define S_ 2048
#define D_ 1024
#define H_ 2048
#define E_ 8
#define NTOK (B_*S_)            /* 8192  */
#define NPAD_MAX 17408          /* 16384 + 8*128 */
#define MTILES (NPAD_MAX/128)   /* 136 */
#define MU_F 0.7f
#define GAMMA_F 1.0f
#define LN_EPS_F 1e-5f
#define WELEMS (E_*D_*H_)          /* 16.78M per weight tensor */
#define CONV2_BLOCKS (WELEMS/2048) /* 8192: 256 thr x 2 float4 */
#define ZERO_BLOCKS ((NTOK*D_)/2048) /* 4096 */

// ------------------------------------------------------------------
// scratch (static __device__; referenced ONLY from device code)
// ------------------------------------------------------------------
__device__ __align__(256) __half g_a1 [(size_t)NPAD_MAX * D_];
__device__ __align__(256) __half g_a2 [(size_t)NPAD_MAX * H_];
__device__ __align__(256) __half g_w1h[(size_t)WELEMS];   // fp16 W1 [e][d][h]
__device__ __align__(256) __half g_w2h[(size_t)WELEMS];   // fp16 W2 [e][h][d]
__device__ __align__(256) float  g_presum[(size_t)NTOK * D_];  // gate-weighted expert sum
__device__ int   g_assign_tok[NPAD_MAX];
__device__ float g_wslot[NPAD_MAX];
__device__ float g_wk   [NTOK * 2];
__device__ int   g_eidx [NTOK * 2];
__device__ int   g_counts [E_];
__device__ int   g_offsets_pad[E_];
__device__ int   g_cursor [E_];

// ------------------------------------------------------------------
// PTX helpers
// ------------------------------------------------------------------
__device__ __forceinline__ uint32_t smem_u32(const void* p) {
    uint32_t a;
    asm("{ .reg .u64 t; cvta.to.shared.u64 t, %1; cvt.u32.u64 %0, t; }" : "=r"(a) : "l"(p));
    return a;
}
#define CP_ASYNC16(dst, src) \
    asm volatile("cp.async.cg.shared.global [%0], [%1], 16;" :: "r"(dst), "l"(src) : "memory")
#define CP_COMMIT() asm volatile("cp.async.commit_group;" ::: "memory")
#define CP_WAIT2()  asm volatile("cp.async.wait_group 2;"  ::: "memory")

#define LDSM4(r0, r1, r2, r3, addr) \
    asm volatile("ldmatrix.sync.aligned.m8n8.x4.shared.b16 {%0,%1,%2,%3}, [%4];" \
                 : "=r"(r0), "=r"(r1), "=r"(r2), "=r"(r3) : "r"(addr))
#define LDSM4T(r0, r1, r2, r3, addr) \
    asm volatile("ldmatrix.sync.aligned.m8n8.x4.trans.shared.b16 {%0,%1,%2,%3}, [%4];" \
                 : "=r"(r0), "=r"(r1), "=r"(r2), "=r"(r3) : "r"(addr))

#define REDADD_F32(addr, val) \
    asm volatile("red.global.add.f32 [%0], %1;" :: "l"(addr), "f"(val) : "memory")

__device__ __forceinline__ void mma_f16(float& c0, float& c1, float& c2, float& c3,
                                        uint32_t a0, uint32_t a1, uint32_t a2, uint32_t a3,
                                        uint32_t b0, uint32_t b1) {
    asm volatile("mma.sync.aligned.m16n8k16.row.col.f32.f16.f16.f32 "
                 "{%0,%1,%2,%3}, {%4,%5,%6,%7}, {%8,%9}, {%0,%1,%2,%3};"
                 : "+f"(c0), "+f"(c1), "+f"(c2), "+f"(c3)
                 : "r"(a0), "r"(a1), "r"(a2), "r"(a3), "r"(b0), "r"(b1));
}

// ------------------------------------------------------------------
// routing kernels
// ------------------------------------------------------------------
__global__ void router_kernel(const float* __restrict__ x,
                              const float* __restrict__ Wg,
                              const float* __restrict__ bg) {
    int gwarp = (blockIdx.x * blockDim.x + threadIdx.x) >> 5;
    int lane  = threadIdx.x & 31;
    if (gwarp >= NTOK) return;
    const float* xr = x + (size_t)gwarp * D_;
    float acc[E_];
#pragma unroll
    for (int e = 0; e < E_; e++) acc[e] = 0.f;
    for (int d = lane; d < D_; d += 32) {
        float xv = xr[d];
        const float4* wr = reinterpret_cast<const float4*>(Wg + (size_t)d * E_);
        float4 w0 = wr[0], w1 = wr[1];
        acc[0] += xv * w0.x; acc[1] += xv * w0.y; acc[2] += xv * w0.z; acc[3] += xv * w0.w;
        acc[4] += xv * w1.x; acc[5] += xv * w1.y; acc[6] += xv * w1.z; acc[7] += xv * w1.w;
    }
#pragma unroll
    for (int e = 0; e < E_; e++)
#pragma unroll
        for (int o = 16; o > 0; o >>= 1)
            acc[e] += __shfl_xor_sync(0xffffffffu, acc[e], o);
    if (lane == 0) {
        float lg[E_];
#pragma unroll
        for (int e = 0; e < E_; e++) lg[e] = acc[e] + bg[e];
        int i0 = 0;
#pragma unroll
        for (int e = 1; e < E_; e++) if (lg[e] > lg[i0]) i0 = e;
        int i1 = -1;
#pragma unroll
        for (int e = 0; e < E_; e++) {
            if (e == i0) continue;
            if (i1 < 0 || lg[e] > lg[i1]) i1 = e;
        }
        float e1 = __expf(lg[i1] - lg[i0]);
        float inv = 1.f / (1.f + e1);
        g_eidx[gwarp*2]   = i0;  g_eidx[gwarp*2+1] = i1;
        g_wk  [gwarp*2]   = inv; g_wk  [gwarp*2+1] = e1 * inv;
    }
}

// single block: count experts, compute padded offsets, init cursors
__global__ void countoffs_kernel() {
    __shared__ int scnt[E_];
    const int tid = threadIdx.x;
    if (tid < E_) scnt[tid] = 0;
    __syncthreads();
    int local[E_];
#pragma unroll
    for (int e = 0; e < E_; e++) local[e] = 0;
    for (int i = tid; i < NTOK * 2; i += 256) {
        int v = g_eidx[i];
#pragma unroll
        for (int e = 0; e < E_; e++) local[e] += (v == e) ? 1 : 0;
    }
#pragma unroll
    for (int e = 0; e < E_; e++)
        if (local[e]) atomicAdd(&scnt[e], local[e]);
    __syncthreads();
    if (tid == 0) {
        int acc = 0;
        for (int e = 0; e < E_; e++) {
            g_counts[e]      = scnt[e];
            g_offsets_pad[e] = acc;
            g_cursor[e]      = acc;
            acc += (scnt[e] + 127) & ~127;
        }
    }
}

__global__ void scatter_kernel() {
    int t = blockIdx.x * blockDim.x + threadIdx.x;
    if (t >= NTOK) return;
#pragma unroll
    for (int k = 0; k < 2; k++) {
        int e = g_eidx[t*2 + k];
        int pos = atomicAdd(&g_cursor[e], 1);
        g_assign_tok[pos] = t;
        g_wslot[pos]      = g_wk[t*2 + k];
    }
}

// fused prep:
//  blocks [0, NPAD_MAX)                   gather x rows -> fp16 A1 (zero pads)
//  blocks [.., +CONV2)                    convert W1 fp32->fp16 (2 float4/thr)
//  blocks [.., +CONV2)                    convert W2 fp32->fp16
//  blocks [.., +ZERO)                     zero g_presum (2 float4/thr)
__global__ void prep_kernel(const float* __restrict__ x,
                            const float* __restrict__ W1,
                            const float* __restrict__ W2) {
    const int b = blockIdx.x;
    const int tid = threadIdx.x;
    if (b < NPAD_MAX) {
        const int slot = b;
        int e = 0;
#pragma unroll
        for (int k = 1; k < E_; k++) if (slot >= g_offsets_pad[k]) e = k;
        const bool pad = (slot - g_offsets_pad[e]) >= g_counts[e];
        uint2 pk = make_uint2(0u, 0u);
        if (!pad) {
            const int t = g_assign_tok[slot];
            float4 v = reinterpret_cast<const float4*>(x + (size_t)t * D_)[tid];
            __half2 p0 = __floats2half2_rn(v.x, v.y);
            __half2 p1 = __floats2half2_rn(v.z, v.w);
            pk.x = *reinterpret_cast<uint32_t*>(&p0);
            pk.y = *reinterpret_cast<uint32_t*>(&p1);
        }
        reinterpret_cast<uint2*>(g_a1 + (size_t)slot * D_)[tid] = pk;
    } else if (b < NPAD_MAX + 2 * CONV2_BLOCKS) {
        const int cb = b - NPAD_MAX;
        const bool w2 = (cb >= CONV2_BLOCKS);
        const int cbb = w2 ? (cb - CONV2_BLOCKS) : cb;
        const float* src = w2 ? W2 : W1;
        __half* dst = w2 ? g_w2h : g_w1h;
#pragma unroll
        for (int j = 0; j < 2; j++) {
            const size_t i4 = (size_t)cbb * 512 + j * 256 + tid;   // float4 index
            float4 v = reinterpret_cast<const float4*>(src)[i4];
            __half2 p0 = __floats2half2_rn(v.x, v.y);
            __half2 p1 = __floats2half2_rn(v.z, v.w);
            uint2 pk;
            pk.x = *reinterpret_cast<uint32_t*>(&p0);
            pk.y = *reinterpret_cast<uint32_t*>(&p1);
            reinterpret_cast<uint2*>(dst)[i4] = pk;
        }
    } else {
        const int zb = b - NPAD_MAX - 2 * CONV2_BLOCKS;
        float4 z = make_float4(0.f, 0.f, 0.f, 0.f);
#pragma unroll
        for (int j = 0; j < 2; j++) {
            const size_t i4 = (size_t)zb * 512 + j * 256 + tid;
            reinterpret_cast<float4*>(g_presum)[i4] = z;
        }
    }
}

// ------------------------------------------------------------------
// fp16 mma.sync grouped GEMM: CTA 128x128, 8 warps (warp tile 64x32),
// BK=64, 3-stage cp.async, __launch_bounds__(256,2) => 2 CTAs/SM.
// A: m-major rows 128B, swizzle c^(r&7), LDSM non-trans.
// B: K-major rows 256B, swizzle c^(r&15), LDSM.trans.
// PHASE1 epilogue: relu+bias -> fp16 -> g_a2.
// PHASE2 epilogue: gate-weighted red.global.add into g_presum (pad-guarded).
// ------------------------------------------------------------------
#define STAGE_SZ 32768           /* A 16KB + B 16KB */
#define SMEM_TOTAL (3*STAGE_SZ)  /* 98304; x2 CTAs = 192KB <= 228KB */

template<int KD, int ND, bool PHASE1>
__global__ void __launch_bounds__(256, 2)
moe_mma_kernel(const float* __restrict__ bias) {
    constexpr int NSLAB = KD / 64;
    const int e   = blockIdx.z;
    const int cnt = g_counts[e];
    const int m0  = blockIdx.y * 128;
    if (m0 >= cnt) return;
    const int off = g_offsets_pad[e];
    const int n0  = blockIdx.x * 128;

    const __half* A  = PHASE1 ? g_a1  : g_a2;
    const __half* Bw = PHASE1 ? g_w1h : g_w2h;

    extern __shared__ char smem[];
    const uint32_t sb = smem_u32(smem);
    const int tid  = threadIdx.x;
    const int wid  = tid >> 5;
    const int lane = tid & 31;
    const int lr   = lane >> 2;      // 0..7
    const int lc   = lane & 3;       // 0..3
    const int warp_m = (wid & 1) * 64;
    const int warp_n = (wid >> 1) * 32;

    const size_t arow = (size_t)(off + m0);
    const __half* Bb = Bw + (size_t)e * KD * ND + n0;   // row k: +k*ND

    float acc[4][4][4];
#pragma unroll
    for (int mt = 0; mt < 4; mt++)
#pragma unroll
        for (int nt = 0; nt < 4; nt++)
#pragma unroll
            for (int c = 0; c < 4; c++) acc[mt][nt][c] = 0.f;

    auto load_stage = [&](int s) {
        const uint32_t stage = sb + (uint32_t)(s % 3) * STAGE_SZ;
        const int k0 = s * 64;
#pragma unroll
        for (int j = 0; j < 8; j++) {
            const int cid = tid + j * 256;          // 0..2047
            if (cid < 1024) {
                const int r = cid >> 3, c = cid & 7;
                const __half* src = A + (arow + r) * KD + k0 + c * 8;
                const uint32_t dst = stage + (uint32_t)r * 128u
                                   + (uint32_t)((c ^ (r & 7)) << 4);
                CP_ASYNC16(dst, src);
            } else {
                const int loc = cid - 1024;
                const int r = loc >> 4, c = loc & 15;     // k-row, n-chunk
                const __half* src = Bb + (size_t)(k0 + r) * ND + c * 8;
                const uint32_t dst = stage + 16384u + (uint32_t)r * 256u
                                   + (uint32_t)((c ^ (r & 15)) << 4);
                CP_ASYNC16(dst, src);
            }
        }
        CP_COMMIT();
    };

    load_stage(0);
    if (NSLAB > 1) load_stage(1); else CP_COMMIT();

    const int a_row_l = warp_m + (lane & 7) + ((lane >> 3) & 1) * 8;  // + mt*16
    const int a_kh    = lane >> 4;
    const int b_m     = lane >> 3;
    const int b_nt_l  = b_m >> 1;
    const int b_kh    = b_m & 1;
    const int b_r15   = b_kh * 8 + (lane & 7);
    const int b_cb    = (warp_n >> 3) + b_nt_l;

    for (int s = 0; s < NSLAB; s++) {
        if (s + 2 < NSLAB) load_stage(s + 2); else CP_COMMIT();
        CP_WAIT2();
        __syncthreads();

        const uint32_t stage = sb + (uint32_t)(s % 3) * STAGE_SZ;
        const uint32_t sA = stage;
        const uint32_t sB = stage + 16384u;

#pragma unroll
        for (int ks = 0; ks < 4; ks++) {
            uint32_t a[4][4], b[8];
#pragma unroll
            for (int p = 0; p < 2; p++) {
                const int krow = ks * 16 + b_r15;
                const int cch  = (b_cb + p * 2) ^ b_r15;
                const uint32_t addr = sB + (uint32_t)krow * 256u
                                    + (uint32_t)(cch << 4);
                LDSM4T(b[p*4+0], b[p*4+1], b[p*4+2], b[p*4+3], addr);
            }
#pragma unroll
            for (int mt = 0; mt < 4; mt++) {
                const int mrow = a_row_l + mt * 16;
                const int kch  = ks * 2 + a_kh;
                const uint32_t addr = sA + (uint32_t)mrow * 128u
                                    + (uint32_t)((kch ^ (mrow & 7)) << 4);
                LDSM4(a[mt][0], a[mt][1], a[mt][2], a[mt][3], addr);
            }
#pragma unroll
            for (int mt = 0; mt < 4; mt++)
#pragma unroll
                for (int nt = 0; nt < 4; nt++)
                    mma_f16(acc[mt][nt][0], acc[mt][nt][1], acc[mt][nt][2], acc[mt][nt][3],
                            a[mt][0], a[mt][1], a[mt][2], a[mt][3],
                            b[nt*2], b[nt*2+1]);
        }
        __syncthreads();
    }

    // ---------------- epilogue (from registers) ----------------
#pragma unroll
    for (int mt = 0; mt < 4; mt++) {
        const size_t r0 = arow + warp_m + mt*16 + lr;
        const size_t r1 = r0 + 8;
        if (PHASE1) {
#pragma unroll
            for (int nt = 0; nt < 4; nt++) {
                const int col = n0 + warp_n + nt*8 + lc*2;
                const float bv0 = bias[(size_t)e * ND + col];
                const float bv1 = bias[(size_t)e * ND + col + 1];
                float v0 = fmaxf(acc[mt][nt][0] + bv0, 0.f);
                float v1 = fmaxf(acc[mt][nt][1] + bv1, 0.f);
                float v2 = fmaxf(acc[mt][nt][2] + bv0, 0.f);
                float v3 = fmaxf(acc[mt][nt][3] + bv1, 0.f);
                __half2 p0 = __floats2half2_rn(v0, v1);
                __half2 p1 = __floats2half2_rn(v2, v3);
                *reinterpret_cast<__half2*>(g_a2 + r0 * H_ + col) = p0;
                *reinterpret_cast<__half2*>(g_a2 + r1 * H_ + col) = p1;
            }
        } else {
            const bool valid0 = (int)(r0 - off) < cnt;
            const bool valid1 = (int)(r1 - off) < cnt;
            const int  t0 = valid0 ? g_assign_tok[r0] : 0;
            const int  t1 = valid1 ? g_assign_tok[r1] : 0;
            const float w0 = valid0 ? g_wslot[r0] : 0.f;
            const float w1 = valid1 ? g_wslot[r1] : 0.f;
            float* p0 = g_presum + (size_t)t0 * D_;
            float* p1 = g_presum + (size_t)t1 * D_;
#pragma unroll
            for (int nt = 0; nt < 4; nt++) {
                const int col = n0 + warp_n + nt*8 + lc*2;
                const float bv0 = bias[(size_t)e * ND + col];
                const float bv1 = bias[(size_t)e * ND + col + 1];
                if (valid0) {
                    REDADD_F32(p0 + col,     w0 * (acc[mt][nt][0] + bv0));
                    REDADD_F32(p0 + col + 1, w0 * (acc[mt][nt][1] + bv1));
                }
                if (valid1) {
                    REDADD_F32(p1 + col,     w1 * (acc[mt][nt][2] + bv0));
                    REDADD_F32(p1 + col + 1, w1 * (acc[mt][nt][3] + bv1));
                }
            }
        }
    }
}

// ------------------------------------------------------------------
// combine: presum -> momentum -> residual -> LayerNorm
// ------------------------------------------------------------------
__global__ void combine_kernel(const float* __restrict__ x,
                               const float* __restrict__ momentum,
                               const float* __restrict__ ln_g,
                               const float* __restrict__ ln_b,
                               float* __restrict__ out) {
    const int t   = blockIdx.x;
    const int tid = threadIdx.x;
    const float* ps  = g_presum  + (size_t)t * D_;
    const float* xr  = x         + (size_t)t * D_;
    const float* mr  = momentum  + (size_t)t * D_;

    float ov[4], nmv[4];
    float sum = 0.f, sumsq = 0.f;
#pragma unroll
    for (int i = 0; i < 4; i++) {
        int d = tid + i * 256;
        float nm  = -ps[d] + MU_F * mr[d];
        float o   = xr[d] + GAMMA_F * nm;
        nmv[i] = nm; ov[i] = o;
        sum += o; sumsq += o * o;
    }
#pragma unroll
    for (int o = 16; o > 0; o >>= 1) {
        sum   += __shfl_xor_sync(0xffffffffu, sum,   o);
        sumsq += __shfl_xor_sync(0xffffffffu, sumsq, o);
    }
    __shared__ float red[16];
    const int warp = tid >> 5, lane = tid & 31;
    if (lane == 0) { red[warp] = sum; red[8 + warp] = sumsq; }
    __syncthreads();
    float tot = 0.f, totq = 0.f;
#pragma unroll
    for (int wgi = 0; wgi < 8; wgi++) { tot += red[wgi]; totq += red[8 + wgi]; }
    const float mean = tot * (1.f / D_);
    const float var  = totq * (1.f / D_) - mean * mean;
    const float inv  = rsqrtf(var + LN_EPS_F);
#pragma unroll
    for (int i = 0; i < 4; i++) {
        int d = tid + i * 256;
        out[(size_t)t * D_ + d] = (ov[i] - mean) * inv * ln_g[d] + ln_b[d];
        out[(size_t)(NTOK + t) * D_ + d] = nmv[i];
    }
}

// ------------------------------------------------------------------
// launch
// ------------------------------------------------------------------
extern "C" void kernel_launch(void* const* d_in, const int* in_sizes, int n_in,
                              void* d_out, int out_size) {
    const float* x        = (const float*)d_in[0];
    const float* momentum = (const float*)d_in[1];
    const float* Wg       = (const float*)d_in[2];
    const float* bg       = (const float*)d_in[3];
    const float* W1       = (const float*)d_in[4];
    const float* b1       = (const float*)d_in[5];
    const float* W2       = (const float*)d_in[6];
    const float* b2       = (const float*)d_in[7];
    const float* ln_g     = (const float*)d_in[8];
    const float* ln_b     = (const float*)d_in[9];
    float* out            = (float*)d_out;

    cudaFuncSetAttribute(moe_mma_kernel<D_, H_, true>,
                         cudaFuncAttributeMaxDynamicSharedMemorySize, SMEM_TOTAL);
    cudaFuncSetAttribute(moe_mma_kernel<H_, D_, false>,
                         cudaFuncAttributeMaxDynamicSharedMemorySize, SMEM_TOTAL);

    router_kernel<<<NTOK / 8, 256>>>(x, Wg, bg);
    countoffs_kernel<<<1, 256>>>();
    scatter_kernel<<<NTOK / 256, 256>>>();
    prep_kernel<<<NPAD_MAX + 2 * CONV2_BLOCKS + ZERO_BLOCKS, 256>>>(x, W1, W2);

    {   // GEMM1: A1 @ W1 (K-major B) -> relu+bias -> fp16 -> A2
        dim3 grid(H_ / 128, MTILES, E_);
        moe_mma_kernel<D_, H_, true><<<grid, 256, SMEM_TOTAL>>>(b1);
    }
    {   // GEMM2: A2 @ W2 (K-major B) -> gate-weighted red.add -> g_presum
        dim3 grid(D_ / 128, MTILES, E_);
        moe_mma_kernel<H_, D_, false><<<grid, 256, SMEM_TOTAL>>>(b2);
    }

    combine_kernel<<<NTOK, 256>>>(x, momentum, ln_g, ln_b, out);
}